// round 1
// baseline (speedup 1.0000x reference)
#include <cuda_runtime.h>

#define DIM 1024
#define NQ 10
#define NL 4
#define WPB 8              // warps (rows) per block
#define SWPAD(i) ((i) + ((i) >> 5))   // stride-33 swizzle: conflict-free for all our patterns

__device__ int   g_perm[DIM];
__device__ float g_gates[NL][NQ][4];   // [pass][bit][g00,g01,g10,g11]
__device__ int   g_npasses;

// ---------------------------------------------------------------------------
// Kernel 1: extract permutation from cnot_matrix. perm[i] = j : C[i,j] != 0.
// One warp per row, coalesced scan.
// ---------------------------------------------------------------------------
__global__ void perm_kernel(const float* __restrict__ C) {
    int warp = (blockIdx.x * blockDim.x + threadIdx.x) >> 5;
    int lane = threadIdx.x & 31;
    if (warp >= DIM) return;
    const float* row = C + warp * DIM;
    int found = -1;
    #pragma unroll
    for (int jj = 0; jj < DIM / 32; jj++) {
        int j = jj * 32 + lane;
        if (row[j] != 0.0f) found = j;
    }
    #pragma unroll
    for (int off = 16; off; off >>= 1) {
        int o = __shfl_xor_sync(0xffffffffu, found, off);
        found = max(found, o);
    }
    if (lane == 0) g_perm[warp] = (found >= 0) ? found : warp;
}

// ---------------------------------------------------------------------------
// Kernel 2: build per-bit 2x2 gates from angles; if perm == identity, compose
// all 4 layers into a single pass (product of krons = kron of products).
// ---------------------------------------------------------------------------
__global__ void gates_kernel(const float* __restrict__ angles /* [NL][NQ][3] */) {
    __shared__ float G[NL][NQ][4];
    __shared__ int s_ident;
    int tid = threadIdx.x;                 // 64 threads
    if (tid == 0) s_ident = 1;
    __syncthreads();

    // identity check on perm
    int bad = 0;
    for (int i = tid; i < DIM; i += blockDim.x)
        if (g_perm[i] != i) bad = 1;
    if (bad) atomicExch(&s_ident, 0);

    // per-(layer,qubit) gate: G = R(a2/2) @ R(a1/2) @ R(a0/2)
    if (tid < NL * NQ) {
        int l = tid / NQ, q = tid % NQ;
        const float* a = angles + (size_t)(l * NQ + q) * 3;
        float m0 = 1.f, m1 = 0.f, m2 = 0.f, m3 = 1.f;
        #pragma unroll
        for (int k = 0; k < 3; k++) {
            float h = 0.5f * a[k];
            float c = cosf(h), s = sinf(h);
            // M = R_k @ M,  R_k = [[c,-s],[s,c]]
            float n0 = c * m0 - s * m2;
            float n1 = c * m1 - s * m3;
            float n2 = s * m0 + c * m2;
            float n3 = s * m1 + c * m3;
            m0 = n0; m1 = n1; m2 = n2; m3 = n3;
        }
        G[l][q][0] = m0; G[l][q][1] = m1; G[l][q][2] = m2; G[l][q][3] = m3;
    }
    __syncthreads();

    if (s_ident) {
        // compose: per bit b, H_b = G[3][9-b] @ G[2][9-b] @ G[1][9-b] @ G[0][9-b]
        if (tid < NQ) {
            int b = tid, q = 9 - b;
            float m0 = G[0][q][0], m1 = G[0][q][1], m2 = G[0][q][2], m3 = G[0][q][3];
            #pragma unroll
            for (int l = 1; l < NL; l++) {
                float a0 = G[l][q][0], a1 = G[l][q][1], a2 = G[l][q][2], a3 = G[l][q][3];
                float n0 = a0 * m0 + a1 * m2;
                float n1 = a0 * m1 + a1 * m3;
                float n2 = a2 * m0 + a3 * m2;
                float n3 = a2 * m1 + a3 * m3;
                m0 = n0; m1 = n1; m2 = n2; m3 = n3;
            }
            g_gates[0][b][0] = m0; g_gates[0][b][1] = m1;
            g_gates[0][b][2] = m2; g_gates[0][b][3] = m3;
        }
        if (tid == 0) g_npasses = 1;
        // g_perm is identity -> gather in main kernel is a no-op permutation
    } else {
        if (tid < NL * NQ) {
            int l = tid / NQ, b = tid % NQ, q = 9 - b;
            g_gates[l][b][0] = G[l][q][0]; g_gates[l][b][1] = G[l][q][1];
            g_gates[l][b][2] = G[l][q][2]; g_gates[l][b][3] = G[l][q][3];
        }
        if (tid == 0) g_npasses = NL;
    }
}

// ---------------------------------------------------------------------------
// Main kernel: one warp per row. 32 floats/thread in registers.
// Layout A: r[k] = v[lane*32 + k]  (bits 0..4 intra-thread)
// Layout B: r[k] = v[k*32 + lane]  (bits 5..9 intra-thread)
// Per pass: 5 intra stages (A) -> smem transpose -> 5 intra stages (B)
//           -> smem transpose back with perm folded into the read addresses.
// ---------------------------------------------------------------------------
__global__ __launch_bounds__(32 * WPB)
void qnet_kernel(const float* __restrict__ x, float* __restrict__ out, int nrows) {
    __shared__ float buf[WPB][DIM + DIM / 32];       // 1056 floats per warp
    __shared__ int   sperm[DIM + DIM / 32];          // pre-swizzled: sperm[SW(i)] = SW(perm[i])
    __shared__ float sg[NL][NQ][4];
    __shared__ int   s_np;

    int tid = threadIdx.x;
    for (int i = tid; i < DIM; i += blockDim.x) {
        int p = g_perm[i];
        sperm[SWPAD(i)] = SWPAD(p);
    }
    for (int i = tid; i < NL * NQ * 4; i += blockDim.x)
        ((float*)sg)[i] = ((const float*)g_gates)[i];
    if (tid == 0) s_np = g_npasses;
    __syncthreads();

    int np   = s_np;
    int warp = tid >> 5, lane = tid & 31;
    int row  = blockIdx.x * WPB + warp;
    if (row >= nrows) return;
    float* wb = buf[warp];

    // load row, layout A (8x LDG.128 per thread)
    float r[32];
    const float4* xin = (const float4*)(x + (size_t)row * DIM + lane * 32);
    #pragma unroll
    for (int k4 = 0; k4 < 8; k4++) {
        float4 v = xin[k4];
        r[k4 * 4 + 0] = v.x; r[k4 * 4 + 1] = v.y;
        r[k4 * 4 + 2] = v.z; r[k4 * 4 + 3] = v.w;
    }

    for (int p = 0; p < np; p++) {
        const float(*g)[4] = sg[p];

        // stages on bits 0..4 (intra-thread, layout A)
        #pragma unroll
        for (int b = 0; b < 5; b++) {
            float ga = g[b][0], gb = g[b][1], gc = g[b][2], gd = g[b][3];
            int m = 1 << b;
            #pragma unroll
            for (int k0 = 0; k0 < 32; k0++) {
                if (k0 & m) continue;
                int k1 = k0 | m;
                float x0 = r[k0], x1 = r[k1];
                r[k0] = ga * x0 + gb * x1;
                r[k1] = gc * x0 + gd * x1;
            }
        }

        // transpose A -> B   (write: lane*33+k, read: k*33+lane -- both conflict-free)
        __syncwarp();
        #pragma unroll
        for (int k = 0; k < 32; k++) { int i = lane * 32 + k; wb[SWPAD(i)] = r[k]; }
        __syncwarp();
        #pragma unroll
        for (int k = 0; k < 32; k++) { int i = k * 32 + lane; r[k] = wb[SWPAD(i)]; }

        // stages on bits 5..9 (intra-thread, layout B: bit b of element = bit (b-5) of k)
        #pragma unroll
        for (int b = 5; b < 10; b++) {
            float ga = g[b][0], gb = g[b][1], gc = g[b][2], gd = g[b][3];
            int m = 1 << (b - 5);
            #pragma unroll
            for (int k0 = 0; k0 < 32; k0++) {
                if (k0 & m) continue;
                int k1 = k0 | m;
                float x0 = r[k0], x1 = r[k1];
                r[k0] = ga * x0 + gb * x1;
                r[k1] = gc * x0 + gd * x1;
            }
        }

        // transpose B -> A with permutation folded into the gather addresses
        __syncwarp();
        #pragma unroll
        for (int k = 0; k < 32; k++) { int i = k * 32 + lane; wb[SWPAD(i)] = r[k]; }
        __syncwarp();
        #pragma unroll
        for (int k = 0; k < 32; k++) { int i = lane * 32 + k; r[k] = wb[sperm[SWPAD(i)]]; }
    }

    // store, layout A (8x STG.128 per thread)
    float4* o = (float4*)(out + (size_t)row * DIM + lane * 32);
    #pragma unroll
    for (int k4 = 0; k4 < 8; k4++)
        o[k4] = make_float4(r[k4 * 4 + 0], r[k4 * 4 + 1], r[k4 * 4 + 2], r[k4 * 4 + 3]);
}

// ---------------------------------------------------------------------------
extern "C" void kernel_launch(void* const* d_in, const int* in_sizes, int n_in,
                              void* d_out, int out_size) {
    const float* x      = (const float*)d_in[0];   // [BATCH, 1024]
    const float* angles = (const float*)d_in[1];   // [4, 10, 3]
    const float* cnot   = (const float*)d_in[2];   // [1024, 1024]
    float* out = (float*)d_out;

    int nrows = in_sizes[0] / DIM;

    perm_kernel<<<(DIM * 32 + 255) / 256, 256>>>(cnot);
    gates_kernel<<<1, 64>>>(angles);
    int nblocks = (nrows + WPB - 1) / WPB;
    qnet_kernel<<<nblocks, 32 * WPB>>>(x, out, nrows);
}

// round 4
// speedup vs baseline: 1.6902x; 1.6902x over previous
#include <cuda_runtime.h>

#define DIM 1024
#define NQ 10
#define NL 4
#define WPB 4                         // warps per block (each warp = 2 rows)
#define SWP(i) ((i) + ((i) >> 5))     // stride-33 pad, conflict-free both directions

__device__ int   g_perm[DIM];
__device__ float g_gates[NL][NQ][4];  // [pass][bit][g00,g01,g10,g11]
__device__ int   g_npasses;
__device__ int   g_ident;

typedef unsigned long long u64;

__device__ __forceinline__ u64 pk2(float lo, float hi) {
    u64 r; asm("mov.b64 %0, {%1, %2};" : "=l"(r) : "f"(lo), "f"(hi)); return r;
}
__device__ __forceinline__ void unpk2(u64 v, float& lo, float& hi) {
    asm("mov.b64 {%0, %1}, %2;" : "=f"(lo), "=f"(hi) : "l"(v));
}
__device__ __forceinline__ u64 fma2(u64 a, u64 b, u64 c) {   // a*b+c elementwise
    u64 d; asm("fma.rn.f32x2 %0, %1, %2, %3;" : "=l"(d) : "l"(a), "l"(b), "l"(c)); return d;
}
__device__ __forceinline__ u64 mul2(u64 a, u64 b) {
    u64 d; asm("mul.rn.f32x2 %0, %1, %2;" : "=l"(d) : "l"(a), "l"(b)); return d;
}

// ---------------------------------------------------------------------------
// Prep: perm via diagonal shortcut (full row scan only if diag==0), identity
// flag, per-bit gates, and 4->1 layer composition when perm == identity.
// One block, 1024 threads, single launch.
// ---------------------------------------------------------------------------
__global__ void prep_kernel(const float* __restrict__ C,
                            const float* __restrict__ angles) {
    __shared__ int s_ident;
    __shared__ float G[NL][NQ][4];
    int tid = threadIdx.x;
    if (tid == 0) s_ident = 1;
    __syncthreads();

    // permutation-matrix row i: perm[i]=i iff C[i][i] != 0
    {
        int p = tid;
        float d = C[(size_t)tid * DIM + tid];
        if (d == 0.0f) {
            atomicExch(&s_ident, 0);
            const float* row = C + (size_t)tid * DIM;
            for (int j = 0; j < DIM; j++)
                if (row[j] != 0.0f) { p = j; break; }
        }
        g_perm[tid] = p;
    }

    // per-(layer,qubit) gate: G = R(a2/2) @ R(a1/2) @ R(a0/2)
    if (tid < NL * NQ) {
        int l = tid / NQ, q = tid % NQ;
        const float* a = angles + (size_t)(l * NQ + q) * 3;
        float m0 = 1.f, m1 = 0.f, m2 = 0.f, m3 = 1.f;
        #pragma unroll
        for (int k = 0; k < 3; k++) {
            float h = 0.5f * a[k];
            float c = cosf(h), s = sinf(h);
            float n0 = c * m0 - s * m2, n1 = c * m1 - s * m3;
            float n2 = s * m0 + c * m2, n3 = s * m1 + c * m3;
            m0 = n0; m1 = n1; m2 = n2; m3 = n3;
        }
        G[l][q][0] = m0; G[l][q][1] = m1; G[l][q][2] = m2; G[l][q][3] = m3;
    }
    __syncthreads();

    if (s_ident) {
        if (tid < NQ) {   // compose all 4 layers per bit: H_b = G3 G2 G1 G0
            int b = tid, q = 9 - b;
            float m0 = G[0][q][0], m1 = G[0][q][1], m2 = G[0][q][2], m3 = G[0][q][3];
            #pragma unroll
            for (int l = 1; l < NL; l++) {
                float a0 = G[l][q][0], a1 = G[l][q][1], a2 = G[l][q][2], a3 = G[l][q][3];
                float n0 = a0 * m0 + a1 * m2, n1 = a0 * m1 + a1 * m3;
                float n2 = a2 * m0 + a3 * m2, n3 = a2 * m1 + a3 * m3;
                m0 = n0; m1 = n1; m2 = n2; m3 = n3;
            }
            g_gates[0][b][0] = m0; g_gates[0][b][1] = m1;
            g_gates[0][b][2] = m2; g_gates[0][b][3] = m3;
        }
        if (tid == 0) { g_npasses = 1; g_ident = 1; }
    } else {
        if (tid < NL * NQ) {
            int l = tid / NQ, b = tid % NQ, q = 9 - b;
            g_gates[l][b][0] = G[l][q][0]; g_gates[l][b][1] = G[l][q][1];
            g_gates[l][b][2] = G[l][q][2]; g_gates[l][b][3] = G[l][q][3];
        }
        if (tid == 0) { g_npasses = NL; g_ident = 0; }
    }
}

// ---------------------------------------------------------------------------
// Main: one warp per TWO rows, f32x2 packed butterflies.
// Layout A: r[k] = v[lane*32 + k]  (bits 0..4 intra-thread)
// Layout B: r[k] = v[k*32 + lane]  (bits 5..9 intra-thread)
// Fused path: load A -> bits 0-4 -> transpose -> bits 5-9 -> store B (coalesced).
// General path: per pass do both transposes with perm gather; store A.
// ---------------------------------------------------------------------------
__global__ __launch_bounds__(32 * WPB)
void qnet_kernel(const float* __restrict__ x, float* __restrict__ out, int nrows) {
    __shared__ u64 buf[WPB][DIM + DIM / 32];   // 8448 B per warp
    __shared__ int sperm[DIM + DIM / 32];      // pre-swizzled perm (general path only)

    int tid  = threadIdx.x;
    int np    = g_npasses;
    int ident = g_ident;
    bool fused = (np == 1) && ident;

    if (!fused) {
        for (int i = tid; i < DIM; i += blockDim.x)
            sperm[SWP(i)] = SWP(g_perm[i]);
        __syncthreads();
    }

    int warp = tid >> 5, lane = tid & 31;
    int pairi = blockIdx.x * WPB + warp;
    int row0 = pairi * 2;
    if (row0 >= nrows) return;
    int row1 = (row0 + 1 < nrows) ? row0 + 1 : row0;
    u64* wb = buf[warp];

    // ---- load both rows, layout A, pack {row0, row1} into f32x2 ----
    u64 r[32];
    {
        const float4* p0 = (const float4*)(x + (size_t)row0 * DIM + lane * 32);
        const float4* p1 = (const float4*)(x + (size_t)row1 * DIM + lane * 32);
        #pragma unroll
        for (int k4 = 0; k4 < 8; k4++) {
            float4 v0 = p0[k4], v1 = p1[k4];
            r[k4 * 4 + 0] = pk2(v0.x, v1.x);
            r[k4 * 4 + 1] = pk2(v0.y, v1.y);
            r[k4 * 4 + 2] = pk2(v0.z, v1.z);
            r[k4 * 4 + 3] = pk2(v0.w, v1.w);
        }
    }

    for (int p = 0; p < np; p++) {
        const float(*g)[4] = g_gates[p];

        // ---- bits 0..4 (intra-thread, layout A) ----
        #pragma unroll
        for (int b = 0; b < 5; b++) {
            u64 ga = pk2(g[b][0], g[b][0]), gb = pk2(g[b][1], g[b][1]);
            u64 gc = pk2(g[b][2], g[b][2]), gd = pk2(g[b][3], g[b][3]);
            int m = 1 << b;
            #pragma unroll
            for (int k0 = 0; k0 < 32; k0++) {
                if (k0 & m) continue;
                int k1 = k0 | m;
                u64 x0 = r[k0], x1 = r[k1];
                r[k0] = fma2(ga, x0, mul2(gb, x1));
                r[k1] = fma2(gc, x0, mul2(gd, x1));
            }
        }

        // ---- transpose A -> B (LDS.64/STS.64, conflict-free) ----
        __syncwarp();
        #pragma unroll
        for (int k = 0; k < 32; k++) wb[SWP(lane * 32 + k)] = r[k];
        __syncwarp();
        #pragma unroll
        for (int k = 0; k < 32; k++) r[k] = wb[SWP(k * 32 + lane)];

        // ---- bits 5..9 (intra-thread, layout B) ----
        #pragma unroll
        for (int b = 5; b < 10; b++) {
            u64 ga = pk2(g[b][0], g[b][0]), gb = pk2(g[b][1], g[b][1]);
            u64 gc = pk2(g[b][2], g[b][2]), gd = pk2(g[b][3], g[b][3]);
            int m = 1 << (b - 5);
            #pragma unroll
            for (int k0 = 0; k0 < 32; k0++) {
                if (k0 & m) continue;
                int k1 = k0 | m;
                u64 x0 = r[k0], x1 = r[k1];
                r[k0] = fma2(ga, x0, mul2(gb, x1));
                r[k1] = fma2(gc, x0, mul2(gd, x1));
            }
        }

        if (fused) break;   // store directly from layout B below

        // ---- general path: transpose B -> A with perm folded into gather ----
        __syncwarp();
        #pragma unroll
        for (int k = 0; k < 32; k++) wb[SWP(k * 32 + lane)] = r[k];
        __syncwarp();
        #pragma unroll
        for (int k = 0; k < 32; k++) r[k] = wb[sperm[SWP(lane * 32 + k)]];
    }

    if (fused) {
        // store layout B: element i = k*32+lane, coalesced STG.32 per k
        float* o0 = out + (size_t)row0 * DIM + lane;
        float* o1 = out + (size_t)row1 * DIM + lane;
        #pragma unroll
        for (int k = 0; k < 32; k++) {
            float lo, hi; unpk2(r[k], lo, hi);
            o0[k * 32] = lo;
            o1[k * 32] = hi;
        }
    } else {
        // store layout A: 8x STG.128 per row
        float4* o0 = (float4*)(out + (size_t)row0 * DIM + lane * 32);
        float4* o1 = (float4*)(out + (size_t)row1 * DIM + lane * 32);
        #pragma unroll
        for (int k4 = 0; k4 < 8; k4++) {
            float4 v0, v1;
            unpk2(r[k4 * 4 + 0], v0.x, v1.x);
            unpk2(r[k4 * 4 + 1], v0.y, v1.y);
            unpk2(r[k4 * 4 + 2], v0.z, v1.z);
            unpk2(r[k4 * 4 + 3], v0.w, v1.w);
            o0[k4] = v0; o1[k4] = v1;
        }
    }
}

// ---------------------------------------------------------------------------
extern "C" void kernel_launch(void* const* d_in, const int* in_sizes, int n_in,
                              void* d_out, int out_size) {
    const float* x      = (const float*)d_in[0];   // [BATCH, 1024]
    const float* angles = (const float*)d_in[1];   // [4, 10, 3]
    const float* cnot   = (const float*)d_in[2];   // [1024, 1024]
    float* out = (float*)d_out;

    int nrows = in_sizes[0] / DIM;

    prep_kernel<<<1, DIM>>>(cnot, angles);
    int npairs  = (nrows + 1) / 2;
    int nblocks = (npairs + WPB - 1) / WPB;
    qnet_kernel<<<nblocks, 32 * WPB>>>(x, out, nrows);
}